// round 7
// baseline (speedup 1.0000x reference)
#include <cuda_runtime.h>
#include <cstdint>

// Problem constants
#define BB 4
#define NN 16384
#define DD 128
#define PP 100
#define BN (BB * NN)          // 65536 points
#define PPAD 128              // padded projection count

// ---------------- device scratch (no allocations allowed) ----------------
__device__ float g_xp[PP * BN];      // x projections, layout [p][bn]
__device__ float g_yp[PP * BN];      // y projections, layout [p][bn]
__device__ float g_delta[PP * BN];   // transported_proj - x_proj, [p][bn]
__device__ float g_thn[PP * DD];     // normalized thetas, [p][d]
__device__ float g_thn_t[DD * PPAD]; // normalized thetas transposed, [d][p] (p padded w/ 0)

// ---------------- K1: normalize thetas ----------------
__global__ void __launch_bounds__(128) norm_kernel(const float* __restrict__ thetas) {
    int p = blockIdx.x;   // 0..127
    int d = threadIdx.x;  // 0..127
    __shared__ float red[4];
    float v = (p < PP) ? thetas[p * DD + d] : 0.f;
    float ss = v * v;
    #pragma unroll
    for (int o = 16; o; o >>= 1) ss += __shfl_xor_sync(0xFFFFFFFFu, ss, o);
    if ((d & 31) == 0) red[d >> 5] = ss;
    __syncthreads();
    float tot = red[0] + red[1] + red[2] + red[3];
    float w = 0.f;
    if (p < PP) {
        w = v / fmaxf(sqrtf(tot), 1e-12f);
        g_thn[p * DD + d] = w;
    }
    g_thn_t[d * PPAD + p] = w;  // zero for padded p
}

// ---------------- K2: projections (fp32 GEMM, 8x8 per thread) ----------------
#define XT_PITCH 136
#define PROJ_SMEM ((DD * PPAD + DD * XT_PITCH) * 4)

__global__ void __launch_bounds__(256) proj_kernel(const float* __restrict__ x,
                                                   const float* __restrict__ y) {
    extern __shared__ float psm[];
    float* th_s = psm;                 // [d * 128 + p]
    float* xt_s = psm + DD * PPAD;     // [d * 136 + r]
    int tid = threadIdx.x;
    int bn0 = blockIdx.x * 128;

    #pragma unroll
    for (int i = tid; i < DD * PPAD; i += 256) th_s[i] = g_thn_t[i];

    const float* srcs[2] = {x, y};
    float* dsts[2] = {g_xp, g_yp};
    int tx = tid & 15;   // bn lane: bn = bn0 + tx + 16*j
    int ty = tid >> 4;   // p group: p = ty*8 + pi

    for (int a = 0; a < 2; a++) {
        const float* src = srcs[a];
        __syncthreads();  // protect xt_s reuse (also orders th_s load on a==0)
        for (int e = tid; e < DD * 128; e += 256) {
            int r = e >> 7, d = e & 127;
            xt_s[d * XT_PITCH + r] = src[(size_t)(bn0 + r) * DD + d];
        }
        __syncthreads();

        float acc[8][8];
        #pragma unroll
        for (int i = 0; i < 8; i++)
            #pragma unroll
            for (int j = 0; j < 8; j++) acc[i][j] = 0.f;

        #pragma unroll 4
        for (int d = 0; d < DD; d++) {
            float4 a0 = *(const float4*)&th_s[d * PPAD + ty * 8];
            float4 a1 = *(const float4*)&th_s[d * PPAD + ty * 8 + 4];
            float av[8] = {a0.x, a0.y, a0.z, a0.w, a1.x, a1.y, a1.z, a1.w};
            float bv[8];
            #pragma unroll
            for (int j = 0; j < 8; j++) bv[j] = xt_s[d * XT_PITCH + tx + 16 * j];
            #pragma unroll
            for (int pi = 0; pi < 8; pi++)
                #pragma unroll
                for (int j = 0; j < 8; j++) acc[pi][j] = fmaf(av[pi], bv[j], acc[pi][j]);
        }

        float* dst = dsts[a];
        #pragma unroll
        for (int pi = 0; pi < 8; pi++) {
            int p = ty * 8 + pi;
            if (p < PP) {
                #pragma unroll
                for (int j = 0; j < 8; j++)
                    dst[(size_t)p * BN + bn0 + tx + 16 * j] = acc[pi][j];
            }
        }
    }
}

// ---------------- K3: per-(p,b) radix sort + rank + delta ----------------
#define SORT_N 16384
#define SORT_THREADS 1024
#define SORT_WARPS 32
// shared: A(16384 u32) B(16384 u32) Cf(16384 f32) whist(32*256 u32) tot(256 u32)
#define SORT_SMEM ((SORT_N * 3 + SORT_WARPS * 256 + 256) * 4)

__device__ __forceinline__ unsigned f2u(float f) {
    unsigned u = __float_as_uint(f);
    return u ^ ((u >> 31) ? 0xFFFFFFFFu : 0x80000000u);
}
__device__ __forceinline__ float u2f(unsigned u) {
    u ^= (u & 0x80000000u) ? 0x80000000u : 0xFFFFFFFFu;
    return __uint_as_float(u);
}

// One stable 8-bit LSD pass. No register key cache (keys re-read from shared),
// no syncwarps: per-warp private histogram rows updated with shared atomics;
// scatter base broadcast from the group leader via shfl.
__device__ void radix_pass(const unsigned* src, unsigned* dst,
                           unsigned* whist, unsigned* tot, int shift) {
    int tid = threadIdx.x;
    int warp = tid >> 5;
    int lane = tid & 31;
    unsigned* wrow = whist + warp * 256;

    for (int i = tid; i < SORT_WARPS * 256; i += SORT_THREADS) whist[i] = 0;
    __syncthreads();

    int base = warp * 512;
    unsigned lowmask = (1u << lane) - 1u;

    // ---- count ----
    #pragma unroll 4
    for (int r = 0; r < 16; r++) {
        unsigned k = src[base + r * 32 + lane];
        unsigned dg = (k >> shift) & 255u;
        unsigned m = __match_any_sync(0xFFFFFFFFu, dg);
        if ((m & lowmask) == 0)  // leader = lowest lane of digit group
            atomicAdd(&wrow[dg], (unsigned)__popc(m));
    }
    __syncthreads();

    // ---- scan counts over warps per digit (exclusive), totals into tot ----
    if (tid < 256) {
        unsigned run = 0;
        #pragma unroll 8
        for (int w = 0; w < SORT_WARPS; w++) {
            unsigned t = whist[w * 256 + tid];
            whist[w * 256 + tid] = run;
            run += t;
        }
        tot[tid] = run;
    }
    __syncthreads();

    // ---- exclusive scan of 256 digit totals (warp 0, 8 per lane) ----
    if (tid < 32) {
        unsigned v[8], run = 0;
        #pragma unroll
        for (int i = 0; i < 8; i++) {
            unsigned t = tot[tid * 8 + i];
            v[i] = run;
            run += t;
        }
        unsigned e = run;
        #pragma unroll
        for (int o = 1; o < 32; o <<= 1) {
            unsigned n = __shfl_up_sync(0xFFFFFFFFu, e, o);
            if (tid >= o) e += n;
        }
        e -= run;  // exclusive
        #pragma unroll
        for (int i = 0; i < 8; i++) tot[tid * 8 + i] = v[i] + e;
    }
    __syncthreads();

    if (tid < 256) {
        unsigned g = tot[tid];
        #pragma unroll 8
        for (int w = 0; w < SORT_WARPS; w++) whist[w * 256 + tid] += g;
    }
    __syncthreads();

    // ---- scatter (stable: lane order within round, atomic order across rounds,
    //      warp-major via the scan) ----
    #pragma unroll 2
    for (int r = 0; r < 16; r++) {
        unsigned k = src[base + r * 32 + lane];
        unsigned dg = (k >> shift) & 255u;
        unsigned m = __match_any_sync(0xFFFFFFFFu, dg);
        int myrank = __popc(m & lowmask);
        int leader = __ffs(m) - 1;
        unsigned b = 0;
        if (myrank == 0) b = atomicAdd(&wrow[dg], (unsigned)__popc(m));
        b = __shfl_sync(0xFFFFFFFFu, b, leader);
        dst[b + myrank] = k;
    }
    __syncthreads();
}

__device__ void sort_segment(const float* gsrc, unsigned* A, unsigned* Bu,
                             unsigned* whist, unsigned* tot) {
    int tid = threadIdx.x;
    for (int i = tid; i < SORT_N; i += SORT_THREADS) A[i] = f2u(gsrc[i]);
    __syncthreads();
    unsigned* s = A;
    unsigned* d = Bu;
    #pragma unroll 1
    for (int pass = 0; pass < 4; pass++) {
        radix_pass(s, d, whist, tot, pass * 8);
        unsigned* t = s; s = d; d = t;
    }
    // 4 passes -> result back in A
}

__global__ void __launch_bounds__(SORT_THREADS, 1) sort_kernel() {
    extern __shared__ unsigned ssm[];
    unsigned* A = ssm;
    unsigned* Bu = ssm + SORT_N;
    float* Cf = (float*)(ssm + 2 * SORT_N);
    unsigned* whist = ssm + 3 * SORT_N;
    unsigned* tot = whist + SORT_WARPS * 256;

    int seg = blockIdx.x;          // 0..399
    int p = seg >> 2;
    int b = seg & 3;
    size_t base = (size_t)p * BN + (size_t)b * NN;
    int tid = threadIdx.x;

    // sort y, stash y_sorted as floats in Cf
    sort_segment(&g_yp[base], A, Bu, whist, tot);
    for (int i = tid; i < SORT_N; i += SORT_THREADS) Cf[i] = u2f(A[i]);
    __syncthreads();

    // sort x (keys only) -> A holds x_sorted (transformed uints, ascending)
    sort_segment(&g_xp[base], A, Bu, whist, tot);

    // rank each x point by binary search of its own key; delta = y_sorted[rank]-x
    for (int i = tid; i < SORT_N; i += SORT_THREADS) {
        float xv = g_xp[base + i];
        unsigned key = f2u(xv);
        int lo = 0, hi = SORT_N;
        #pragma unroll
        for (int s = 0; s < 14; s++) {
            int mid = (lo + hi) >> 1;
            if (A[mid] < key) lo = mid + 1; else hi = mid;
        }
        g_delta[base + i] = Cf[lo] - xv;
    }
}

// ---------------- K4: out = x + (Delta^T @ Thn)/P ----------------
#define OUT_SMEM (2 * PP * DD * 4)

__global__ void __launch_bounds__(256) out_kernel(const float* __restrict__ x,
                                                  float* __restrict__ out) {
    extern __shared__ float osm[];
    float* dl_s = osm;             // [p][bn_local] 100x128
    float* th_s = osm + PP * DD;   // [p][d]        100x128
    int tid = threadIdx.x;
    int bn0 = blockIdx.x * 128;

    for (int e = tid; e < PP * DD; e += 256) {
        th_s[e] = g_thn[e];
        int p = e >> 7, j = e & 127;
        dl_s[e] = g_delta[(size_t)p * BN + bn0 + j];
    }
    __syncthreads();

    int tx = tid & 15;  // d lane: d = tx + 16*k
    int ty = tid >> 4;  // bn group: bn = bn0 + ty*8 + bi

    float acc[8][8];
    #pragma unroll
    for (int i = 0; i < 8; i++)
        #pragma unroll
        for (int j = 0; j < 8; j++) acc[i][j] = 0.f;

    #pragma unroll 4
    for (int p = 0; p < PP; p++) {
        float4 a0 = *(const float4*)&dl_s[p * DD + ty * 8];
        float4 a1 = *(const float4*)&dl_s[p * DD + ty * 8 + 4];
        float av[8] = {a0.x, a0.y, a0.z, a0.w, a1.x, a1.y, a1.z, a1.w};
        float bv[8];
        #pragma unroll
        for (int k = 0; k < 8; k++) bv[k] = th_s[p * DD + tx + 16 * k];
        #pragma unroll
        for (int bi = 0; bi < 8; bi++)
            #pragma unroll
            for (int k = 0; k < 8; k++) acc[bi][k] = fmaf(av[bi], bv[k], acc[bi][k]);
    }

    const float s = 1.0f / (float)PP;
    #pragma unroll
    for (int bi = 0; bi < 8; bi++) {
        size_t row = (size_t)(bn0 + ty * 8 + bi) * DD;
        #pragma unroll
        for (int k = 0; k < 8; k++) {
            size_t o = row + tx + 16 * k;
            out[o] = x[o] + s * acc[bi][k];
        }
    }
}

// ---------------- launch ----------------
extern "C" void kernel_launch(void* const* d_in, const int* in_sizes, int n_in,
                              void* d_out, int out_size) {
    const float* x = (const float*)d_in[0];
    const float* y = (const float*)d_in[1];
    const float* th = (const float*)d_in[2];
    float* out = (float*)d_out;
    (void)in_sizes; (void)n_in; (void)out_size;

    cudaFuncSetAttribute(proj_kernel, cudaFuncAttributeMaxDynamicSharedMemorySize, PROJ_SMEM);
    cudaFuncSetAttribute(sort_kernel, cudaFuncAttributeMaxDynamicSharedMemorySize, SORT_SMEM);
    cudaFuncSetAttribute(out_kernel,  cudaFuncAttributeMaxDynamicSharedMemorySize, OUT_SMEM);

    norm_kernel<<<128, 128>>>(th);
    proj_kernel<<<512, 256, PROJ_SMEM>>>(x, y);
    sort_kernel<<<PP * BB, SORT_THREADS, SORT_SMEM>>>();
    out_kernel<<<512, 256, OUT_SMEM>>>(x, out);
}

// round 8
// speedup vs baseline: 1.1488x; 1.1488x over previous
#include <cuda_runtime.h>
#include <cub/cub.cuh>
#include <cstdint>

// Problem constants
#define BB 4
#define NN 16384
#define DD 128
#define PP 100
#define BN (BB * NN)          // 65536 points
#define PPAD 128              // padded projection count
#define NSEG (PP * BB)        // 400 independent sort segments
#define NITEMS (PP * BN)      // 6,553,600 keys per sort call

// ---------------- device scratch (no allocations allowed) ----------------
__device__ float g_xp[NITEMS];       // x projections, [p][b][n] (segment-contiguous)
__device__ float g_yp[NITEMS];       // y projections
__device__ float g_xs[NITEMS];       // x sorted per segment
__device__ float g_ys[NITEMS];       // y sorted per segment
__device__ float g_delta[NITEMS];    // transported_proj - x_proj
__device__ float g_thn[PP * DD];     // normalized thetas, [p][d]
__device__ float g_thn_t[DD * PPAD]; // normalized thetas transposed, [d][p] (padded)
__device__ int   g_off[NSEG + 1];    // segment offsets for cub

#define TEMP_BYTES (96u << 20)
__device__ __align__(256) unsigned char g_ctemp[TEMP_BYTES];

// ---------------- K1: normalize thetas ----------------
__global__ void __launch_bounds__(128) norm_kernel(const float* __restrict__ thetas) {
    int p = blockIdx.x;   // 0..127
    int d = threadIdx.x;  // 0..127
    __shared__ float red[4];
    float v = (p < PP) ? thetas[p * DD + d] : 0.f;
    float ss = v * v;
    #pragma unroll
    for (int o = 16; o; o >>= 1) ss += __shfl_xor_sync(0xFFFFFFFFu, ss, o);
    if ((d & 31) == 0) red[d >> 5] = ss;
    __syncthreads();
    float tot = red[0] + red[1] + red[2] + red[3];
    float w = 0.f;
    if (p < PP) {
        w = v / fmaxf(sqrtf(tot), 1e-12f);
        g_thn[p * DD + d] = w;
    }
    g_thn_t[d * PPAD + p] = w;  // zero for padded p
}

// ---------------- K1b: segment offsets for cub ----------------
__global__ void __launch_bounds__(512) off_kernel() {
    int i = threadIdx.x;
    if (i <= NSEG) g_off[i] = i * NN;
}

// ---------------- K2: projections (fp32 GEMM, 8x8 per thread) ----------------
#define XT_PITCH 136
#define PROJ_SMEM ((DD * PPAD + DD * XT_PITCH) * 4)

__global__ void __launch_bounds__(256) proj_kernel(const float* __restrict__ x,
                                                   const float* __restrict__ y) {
    extern __shared__ float psm[];
    float* th_s = psm;                 // [d * 128 + p]
    float* xt_s = psm + DD * PPAD;     // [d * 136 + r]
    int tid = threadIdx.x;
    int bn0 = blockIdx.x * 128;

    #pragma unroll
    for (int i = tid; i < DD * PPAD; i += 256) th_s[i] = g_thn_t[i];

    const float* srcs[2] = {x, y};
    float* dsts[2] = {g_xp, g_yp};
    int tx = tid & 15;   // bn lane: bn = bn0 + tx + 16*j
    int ty = tid >> 4;   // p group: p = ty*8 + pi

    for (int a = 0; a < 2; a++) {
        const float* src = srcs[a];
        __syncthreads();  // protect xt_s reuse (also orders th_s load on a==0)
        for (int e = tid; e < DD * 128; e += 256) {
            int r = e >> 7, d = e & 127;
            xt_s[d * XT_PITCH + r] = src[(size_t)(bn0 + r) * DD + d];
        }
        __syncthreads();

        float acc[8][8];
        #pragma unroll
        for (int i = 0; i < 8; i++)
            #pragma unroll
            for (int j = 0; j < 8; j++) acc[i][j] = 0.f;

        #pragma unroll 4
        for (int d = 0; d < DD; d++) {
            float4 a0 = *(const float4*)&th_s[d * PPAD + ty * 8];
            float4 a1 = *(const float4*)&th_s[d * PPAD + ty * 8 + 4];
            float av[8] = {a0.x, a0.y, a0.z, a0.w, a1.x, a1.y, a1.z, a1.w};
            float bv[8];
            #pragma unroll
            for (int j = 0; j < 8; j++) bv[j] = xt_s[d * XT_PITCH + tx + 16 * j];
            #pragma unroll
            for (int pi = 0; pi < 8; pi++)
                #pragma unroll
                for (int j = 0; j < 8; j++) acc[pi][j] = fmaf(av[pi], bv[j], acc[pi][j]);
        }

        float* dst = dsts[a];
        #pragma unroll
        for (int pi = 0; pi < 8; pi++) {
            int p = ty * 8 + pi;
            if (p < PP) {
                #pragma unroll
                for (int j = 0; j < 8; j++)
                    dst[(size_t)p * BN + bn0 + tx + 16 * j] = acc[pi][j];
            }
        }
    }
}

// ---------------- K3: rank + delta from sorted segments ----------------
// One block per (p,b) segment. Stage x_sorted and y_sorted in shared, then for
// each x point recover its rank by binary search of its own value (exact match:
// the value came from the same array), delta = y_sorted[rank] - x.
#define DELTA_THREADS 1024
#define DELTA_SMEM (2 * NN * 4)   // 128 KB

__global__ void __launch_bounds__(DELTA_THREADS, 1) delta_kernel() {
    extern __shared__ float dsm[];
    float* xs = dsm;        // x_sorted
    float* ys = dsm + NN;   // y_sorted
    int seg = blockIdx.x;
    size_t base = (size_t)seg * NN;
    int tid = threadIdx.x;

    for (int i = tid; i < NN; i += DELTA_THREADS) {
        xs[i] = g_xs[base + i];
        ys[i] = g_ys[base + i];
    }
    __syncthreads();

    for (int i = tid; i < NN; i += DELTA_THREADS) {
        float xv = g_xp[base + i];
        int lo = 0, hi = NN;
        #pragma unroll
        for (int s = 0; s < 14; s++) {   // 2^14 = NN
            int mid = (lo + hi) >> 1;
            if (xs[mid] < xv) lo = mid + 1; else hi = mid;
        }
        g_delta[base + i] = ys[lo] - xv;
    }
}

// ---------------- K4: out = x + (Delta^T @ Thn)/P ----------------
#define OUT_SMEM (2 * PP * DD * 4)

__global__ void __launch_bounds__(256) out_kernel(const float* __restrict__ x,
                                                  float* __restrict__ out) {
    extern __shared__ float osm[];
    float* dl_s = osm;             // [p][bn_local] 100x128
    float* th_s = osm + PP * DD;   // [p][d]        100x128
    int tid = threadIdx.x;
    int bn0 = blockIdx.x * 128;

    for (int e = tid; e < PP * DD; e += 256) {
        th_s[e] = g_thn[e];
        int p = e >> 7, j = e & 127;
        dl_s[e] = g_delta[(size_t)p * BN + bn0 + j];
    }
    __syncthreads();

    int tx = tid & 15;  // d lane: d = tx + 16*k
    int ty = tid >> 4;  // bn group: bn = bn0 + ty*8 + bi

    float acc[8][8];
    #pragma unroll
    for (int i = 0; i < 8; i++)
        #pragma unroll
        for (int j = 0; j < 8; j++) acc[i][j] = 0.f;

    #pragma unroll 4
    for (int p = 0; p < PP; p++) {
        float4 a0 = *(const float4*)&dl_s[p * DD + ty * 8];
        float4 a1 = *(const float4*)&dl_s[p * DD + ty * 8 + 4];
        float av[8] = {a0.x, a0.y, a0.z, a0.w, a1.x, a1.y, a1.z, a1.w};
        float bv[8];
        #pragma unroll
        for (int k = 0; k < 8; k++) bv[k] = th_s[p * DD + tx + 16 * k];
        #pragma unroll
        for (int bi = 0; bi < 8; bi++)
            #pragma unroll
            for (int k = 0; k < 8; k++) acc[bi][k] = fmaf(av[bi], bv[k], acc[bi][k]);
    }

    const float s = 1.0f / (float)PP;
    #pragma unroll
    for (int bi = 0; bi < 8; bi++) {
        size_t row = (size_t)(bn0 + ty * 8 + bi) * DD;
        #pragma unroll
        for (int k = 0; k < 8; k++) {
            size_t o = row + tx + 16 * k;
            out[o] = x[o] + s * acc[bi][k];
        }
    }
}

// ---------------- launch ----------------
extern "C" void kernel_launch(void* const* d_in, const int* in_sizes, int n_in,
                              void* d_out, int out_size) {
    const float* x = (const float*)d_in[0];
    const float* y = (const float*)d_in[1];
    const float* th = (const float*)d_in[2];
    float* out = (float*)d_out;
    (void)in_sizes; (void)n_in; (void)out_size;

    // Resolve device-global scratch pointers (host API, no allocation).
    void *p_xp, *p_yp, *p_xs, *p_ys, *p_off, *p_temp;
    cudaGetSymbolAddress(&p_xp, g_xp);
    cudaGetSymbolAddress(&p_yp, g_yp);
    cudaGetSymbolAddress(&p_xs, g_xs);
    cudaGetSymbolAddress(&p_ys, g_ys);
    cudaGetSymbolAddress(&p_off, g_off);
    cudaGetSymbolAddress(&p_temp, g_ctemp);
    const int* off = (const int*)p_off;

    cudaFuncSetAttribute(proj_kernel,  cudaFuncAttributeMaxDynamicSharedMemorySize, PROJ_SMEM);
    cudaFuncSetAttribute(delta_kernel, cudaFuncAttributeMaxDynamicSharedMemorySize, DELTA_SMEM);
    cudaFuncSetAttribute(out_kernel,   cudaFuncAttributeMaxDynamicSharedMemorySize, OUT_SMEM);

    norm_kernel<<<128, 128>>>(th);
    off_kernel<<<1, 512>>>();
    proj_kernel<<<512, 256, PROJ_SMEM>>>(x, y);

    // Segmented radix sort: keys-only, 400 segments of 16384 fp32.
    size_t tb = 0;
    cub::DeviceSegmentedRadixSort::SortKeys(nullptr, tb,
        (const float*)p_yp, (float*)p_ys, (int)NITEMS, (int)NSEG,
        off, off + 1, 0, 32, (cudaStream_t)0);
    if (tb > TEMP_BYTES) tb = TEMP_BYTES;  // should never trigger
    cub::DeviceSegmentedRadixSort::SortKeys(p_temp, tb,
        (const float*)p_yp, (float*)p_ys, (int)NITEMS, (int)NSEG,
        off, off + 1, 0, 32, (cudaStream_t)0);
    cub::DeviceSegmentedRadixSort::SortKeys(p_temp, tb,
        (const float*)p_xp, (float*)p_xs, (int)NITEMS, (int)NSEG,
        off, off + 1, 0, 32, (cudaStream_t)0);

    delta_kernel<<<NSEG, DELTA_THREADS, DELTA_SMEM>>>();
    out_kernel<<<512, 256, OUT_SMEM>>>(x, out);
}

// round 13
// speedup vs baseline: 1.1629x; 1.0123x over previous
#include <cuda_runtime.h>
#include <cub/block/block_radix_sort.cuh>
#include <cstdint>

// Problem constants
#define BB 4
#define NN 16384
#define DD 128
#define PP 100
#define BN (BB * NN)          // 65536 points
#define PPAD 128              // padded projection count
#define NSEG (PP * BB)        // 400 independent segments
#define NITEMS (PP * BN)      // 6,553,600

// ---------------- device scratch (no allocations allowed) ----------------
__device__ float g_xp[NITEMS];       // x projections, [p][b][n] (segment-contiguous)
__device__ float g_yp[NITEMS];       // y projections
__device__ float g_delta[NITEMS];    // transported_proj - x_proj
__device__ float g_thn[PP * DD];     // normalized thetas, [p][d]
__device__ float g_thn_t[DD * PPAD]; // normalized thetas transposed, [d][p] (padded)

// ---------------- K1: normalize thetas ----------------
__global__ void __launch_bounds__(128) norm_kernel(const float* __restrict__ thetas) {
    int p = blockIdx.x;   // 0..127
    int d = threadIdx.x;  // 0..127
    __shared__ float red[4];
    float v = (p < PP) ? thetas[p * DD + d] : 0.f;
    float ss = v * v;
    #pragma unroll
    for (int o = 16; o; o >>= 1) ss += __shfl_xor_sync(0xFFFFFFFFu, ss, o);
    if ((d & 31) == 0) red[d >> 5] = ss;
    __syncthreads();
    float tot = red[0] + red[1] + red[2] + red[3];
    float w = 0.f;
    if (p < PP) {
        w = v / fmaxf(sqrtf(tot), 1e-12f);
        g_thn[p * DD + d] = w;
    }
    g_thn_t[d * PPAD + p] = w;  // zero for padded p
}

// ---------------- K2: projections (fp32 GEMM, 8x8 per thread) ----------------
#define XT_PITCH 136
#define PROJ_SMEM ((DD * PPAD + DD * XT_PITCH) * 4)

__global__ void __launch_bounds__(256) proj_kernel(const float* __restrict__ x,
                                                   const float* __restrict__ y) {
    extern __shared__ float psm[];
    float* th_s = psm;                 // [d * 128 + p]
    float* xt_s = psm + DD * PPAD;     // [d * 136 + r]
    int tid = threadIdx.x;
    int bn0 = blockIdx.x * 128;

    #pragma unroll
    for (int i = tid; i < DD * PPAD; i += 256) th_s[i] = g_thn_t[i];

    const float* srcs[2] = {x, y};
    float* dsts[2] = {g_xp, g_yp};
    int tx = tid & 15;   // bn lane
    int ty = tid >> 4;   // p group

    for (int a = 0; a < 2; a++) {
        const float* src = srcs[a];
        __syncthreads();
        for (int e = tid; e < DD * 128; e += 256) {
            int r = e >> 7, d = e & 127;
            xt_s[d * XT_PITCH + r] = src[(size_t)(bn0 + r) * DD + d];
        }
        __syncthreads();

        float acc[8][8];
        #pragma unroll
        for (int i = 0; i < 8; i++)
            #pragma unroll
            for (int j = 0; j < 8; j++) acc[i][j] = 0.f;

        #pragma unroll 4
        for (int d = 0; d < DD; d++) {
            float4 a0 = *(const float4*)&th_s[d * PPAD + ty * 8];
            float4 a1 = *(const float4*)&th_s[d * PPAD + ty * 8 + 4];
            float av[8] = {a0.x, a0.y, a0.z, a0.w, a1.x, a1.y, a1.z, a1.w};
            float bv[8];
            #pragma unroll
            for (int j = 0; j < 8; j++) bv[j] = xt_s[d * XT_PITCH + tx + 16 * j];
            #pragma unroll
            for (int pi = 0; pi < 8; pi++)
                #pragma unroll
                for (int j = 0; j < 8; j++) acc[pi][j] = fmaf(av[pi], bv[j], acc[pi][j]);
        }

        float* dst = dsts[a];
        #pragma unroll
        for (int pi = 0; pi < 8; pi++) {
            int p = ty * 8 + pi;
            if (p < PP) {
                #pragma unroll
                for (int j = 0; j < 8; j++)
                    dst[(size_t)p * BN + bn0 + tx + 16 * j] = acc[pi][j];
            }
        }
    }
}

// ---------------- K3: fused block sort (x and y) + rank + delta ----------------
// One block per segment. cub::BlockRadixSort ranks via packed per-thread
// counters + block scan: no shared atomics, no per-key serialization, no
// global ping-pong. Sorted arrays parked in shared; delta computed inline.
#define ST 512
#define IPT 32
typedef cub::BlockRadixSort<float, ST, IPT> BRS;

// dynamic smem: xs (64KB) + ys (64KB) + cub temp (~68KB)
#define SD_SMEM (2 * NN * 4 + (int)sizeof(BRS::TempStorage))

__global__ void __launch_bounds__(ST, 1) sortdelta_kernel() {
    extern __shared__ char sdm[];
    float* xs = (float*)sdm;                       // x_sorted
    float* ys = (float*)(sdm + NN * 4);            // y_sorted
    BRS::TempStorage* temp = (BRS::TempStorage*)(sdm + 2 * NN * 4);

    int seg = blockIdx.x;
    size_t base = (size_t)seg * NN;
    int t = threadIdx.x;

    float keys[IPT];

    // ---- sort y ---- (striped load is fine: keys-only sort is arrangement-agnostic)
    #pragma unroll
    for (int i = 0; i < IPT; i++) keys[i] = g_yp[base + i * ST + t];
    BRS(*temp).SortBlockedToStriped(keys);
    #pragma unroll
    for (int i = 0; i < IPT; i++) ys[i * ST + t] = keys[i];  // conflict-free
    __syncthreads();  // temp reuse

    // ---- sort x ----
    #pragma unroll
    for (int i = 0; i < IPT; i++) keys[i] = g_xp[base + i * ST + t];
    BRS(*temp).SortBlockedToStriped(keys);
    #pragma unroll
    for (int i = 0; i < IPT; i++) xs[i * ST + t] = keys[i];
    __syncthreads();

    // ---- rank via binary search of own value (exact match), delta ----
    for (int i = t; i < NN; i += ST) {
        float xv = g_xp[base + i];
        int lo = 0, hi = NN;
        #pragma unroll
        for (int s = 0; s < 14; s++) {   // 2^14 = NN
            int mid = (lo + hi) >> 1;
            if (xs[mid] < xv) lo = mid + 1; else hi = mid;
        }
        g_delta[base + i] = ys[lo] - xv;
    }
}

// ---------------- K4: out = x + (Delta^T @ Thn)/P ----------------
#define OUT_SMEM (2 * PP * DD * 4)

__global__ void __launch_bounds__(256) out_kernel(const float* __restrict__ x,
                                                  float* __restrict__ out) {
    extern __shared__ float osm[];
    float* dl_s = osm;             // [p][bn_local] 100x128
    float* th_s = osm + PP * DD;   // [p][d]        100x128
    int tid = threadIdx.x;
    int bn0 = blockIdx.x * 128;

    for (int e = tid; e < PP * DD; e += 256) {
        th_s[e] = g_thn[e];
        int p = e >> 7, j = e & 127;
        dl_s[e] = g_delta[(size_t)p * BN + bn0 + j];
    }
    __syncthreads();

    int tx = tid & 15;  // d lane: d = tx + 16*k
    int ty = tid >> 4;  // bn group: bn = bn0 + ty*8 + bi

    float acc[8][8];
    #pragma unroll
    for (int i = 0; i < 8; i++)
        #pragma unroll
        for (int j = 0; j < 8; j++) acc[i][j] = 0.f;

    #pragma unroll 4
    for (int p = 0; p < PP; p++) {
        float4 a0 = *(const float4*)&dl_s[p * DD + ty * 8];
        float4 a1 = *(const float4*)&dl_s[p * DD + ty * 8 + 4];
        float av[8] = {a0.x, a0.y, a0.z, a0.w, a1.x, a1.y, a1.z, a1.w};
        float bv[8];
        #pragma unroll
        for (int k = 0; k < 8; k++) bv[k] = th_s[p * DD + tx + 16 * k];
        #pragma unroll
        for (int bi = 0; bi < 8; bi++)
            #pragma unroll
            for (int k = 0; k < 8; k++) acc[bi][k] = fmaf(av[bi], bv[k], acc[bi][k]);
    }

    const float s = 1.0f / (float)PP;
    #pragma unroll
    for (int bi = 0; bi < 8; bi++) {
        size_t row = (size_t)(bn0 + ty * 8 + bi) * DD;
        #pragma unroll
        for (int k = 0; k < 8; k++) {
            size_t o = row + tx + 16 * k;
            out[o] = x[o] + s * acc[bi][k];
        }
    }
}

// ---------------- launch ----------------
extern "C" void kernel_launch(void* const* d_in, const int* in_sizes, int n_in,
                              void* d_out, int out_size) {
    const float* x = (const float*)d_in[0];
    const float* y = (const float*)d_in[1];
    const float* th = (const float*)d_in[2];
    float* out = (float*)d_out;
    (void)in_sizes; (void)n_in; (void)out_size;

    cudaFuncSetAttribute(proj_kernel,      cudaFuncAttributeMaxDynamicSharedMemorySize, PROJ_SMEM);
    cudaFuncSetAttribute(sortdelta_kernel, cudaFuncAttributeMaxDynamicSharedMemorySize, SD_SMEM);
    cudaFuncSetAttribute(out_kernel,       cudaFuncAttributeMaxDynamicSharedMemorySize, OUT_SMEM);

    norm_kernel<<<128, 128>>>(th);
    proj_kernel<<<512, 256, PROJ_SMEM>>>(x, y);
    sortdelta_kernel<<<NSEG, ST, SD_SMEM>>>();
    out_kernel<<<512, 256, OUT_SMEM>>>(x, out);
}